// round 1
// baseline (speedup 1.0000x reference)
#include <cuda_runtime.h>
#include <cfloat>
#include <cstdint>
#include <math.h>

#define BB 4
#define NN 8192
#define KNN 10
#define MTOT (BB*NN)

// ---------------- scratch (device globals; no allocation allowed) ----------------
__device__ float    g_x0[MTOT*6];       // [t, t] duplicated input features
__device__ float    g_x1[MTOT*64];
__device__ float    g_x2[MTOT*64];
__device__ float    g_x3[MTOT*64];
__device__ int      g_knn[MTOT*KNN];
__device__ unsigned g_x5max[BB*1024];   // ordered-uint encoded float max
__device__ float    g_bias7[BB*256];
__device__ float    g_ya[MTOT*256];
__device__ float    g_yb[MTOT*256];

// ---------------- helpers ----------------
__device__ __forceinline__ float prelu_f(float v, float a){ return v >= 0.f ? v : a*v; }

// monotone float->uint encoding for atomicMax on floats
__device__ __forceinline__ unsigned enc_f(float f){
    unsigned u = __float_as_uint(f);
    return (u & 0x80000000u) ? ~u : (u | 0x80000000u);
}
__device__ __forceinline__ float dec_f(unsigned u){
    return (u & 0x80000000u) ? __uint_as_float(u & 0x7fffffffu) : __uint_as_float(~u);
}

// register-resident top-10 insertion (ascending dist; stable: equal dist keeps smaller idx)
__device__ __forceinline__ void topk_insert(float (&dist)[KNN], int (&idx)[KNN], float d, int j){
    if (d < dist[KNN-1]){
        float cd = d; int cj = j;
#pragma unroll
        for (int p = 0; p < KNN; p++){
            if (cd < dist[p]){
                float td = dist[p]; int tj = idx[p];
                dist[p] = cd; idx[p] = cj;
                cd = td; cj = tj;
            }
        }
    }
}

// ---------------- build x0 = concat(targets, targets) ----------------
__global__ __launch_bounds__(256) void build_x0_kernel(const float* __restrict__ t){
    int i = blockIdx.x*256 + threadIdx.x;   // [0, MTOT)
    float t0 = t[i*3+0], t1 = t[i*3+1], t2 = t[i*3+2];
    float* o = g_x0 + (size_t)i*6;
    o[0]=t0; o[1]=t1; o[2]=t2; o[3]=t0; o[4]=t1; o[5]=t2;
}

// ---------------- kNN: per query, top-10 smallest squared distances ----------------
template<int C>
__global__ __launch_bounds__(256) void knn_kernel(const float* __restrict__ x, int* __restrict__ knnout){
    constexpr int TS = 128;
    __shared__ __align__(16) float sf[TS*C];
    __shared__ float sn[TS];
    const int b = blockIdx.y;
    const int q = blockIdx.x*256 + threadIdx.x;
    const float* xb = x + (size_t)b*NN*C;

    float qf[C];
#pragma unroll
    for (int c = 0; c < C; c++) qf[c] = xb[(size_t)q*C + c];
    float qn = 0.f;
#pragma unroll
    for (int c = 0; c < C; c++) qn = fmaf(qf[c], qf[c], qn);

    float dist[KNN]; int idx[KNN];
#pragma unroll
    for (int i = 0; i < KNN; i++){ dist[i] = FLT_MAX; idx[i] = 0x7fffffff; }

    for (int t0 = 0; t0 < NN; t0 += TS){
        __syncthreads();
        for (int i = threadIdx.x; i < TS*C; i += 256) sf[i] = xb[(size_t)t0*C + i];
        __syncthreads();
        if (threadIdx.x < TS){
            float s = 0.f;
#pragma unroll
            for (int c = 0; c < C; c++){ float v = sf[threadIdx.x*C + c]; s = fmaf(v, v, s); }
            sn[threadIdx.x] = s;
        }
        __syncthreads();

        for (int cc = 0; cc < TS; cc += 4){
            float d0=0.f, d1=0.f, d2=0.f, d3=0.f;
            if constexpr ((C & 3) == 0){
#pragma unroll
                for (int c = 0; c < C; c += 4){
                    float4 s0 = *(const float4*)&sf[(cc+0)*C + c];
                    float4 s1 = *(const float4*)&sf[(cc+1)*C + c];
                    float4 s2 = *(const float4*)&sf[(cc+2)*C + c];
                    float4 s3 = *(const float4*)&sf[(cc+3)*C + c];
                    d0=fmaf(qf[c],s0.x,d0); d0=fmaf(qf[c+1],s0.y,d0); d0=fmaf(qf[c+2],s0.z,d0); d0=fmaf(qf[c+3],s0.w,d0);
                    d1=fmaf(qf[c],s1.x,d1); d1=fmaf(qf[c+1],s1.y,d1); d1=fmaf(qf[c+2],s1.z,d1); d1=fmaf(qf[c+3],s1.w,d1);
                    d2=fmaf(qf[c],s2.x,d2); d2=fmaf(qf[c+1],s2.y,d2); d2=fmaf(qf[c+2],s2.z,d2); d2=fmaf(qf[c+3],s2.w,d2);
                    d3=fmaf(qf[c],s3.x,d3); d3=fmaf(qf[c+1],s3.y,d3); d3=fmaf(qf[c+2],s3.z,d3); d3=fmaf(qf[c+3],s3.w,d3);
                }
            } else {
#pragma unroll
                for (int c = 0; c < C; c++){
                    float qv = qf[c];
                    d0 = fmaf(qv, sf[(cc+0)*C + c], d0);
                    d1 = fmaf(qv, sf[(cc+1)*C + c], d1);
                    d2 = fmaf(qv, sf[(cc+2)*C + c], d2);
                    d3 = fmaf(qv, sf[(cc+3)*C + c], d3);
                }
            }
            float b0 = (qn + sn[cc+0]) - 2.f*d0;
            float b1 = (qn + sn[cc+1]) - 2.f*d1;
            float b2 = (qn + sn[cc+2]) - 2.f*d2;
            float b3 = (qn + sn[cc+3]) - 2.f*d3;
            topk_insert(dist, idx, b0, t0+cc+0);
            topk_insert(dist, idx, b1, t0+cc+1);
            topk_insert(dist, idx, b2, t0+cc+2);
            topk_insert(dist, idx, b3, t0+cc+3);
        }
    }
    int* ko = knnout + ((size_t)b*NN + q)*KNN;
#pragma unroll
    for (int i = 0; i < KNN; i++) ko[i] = idx[i];
}

// ---------------- EdgeConv: fused edge-feature MLP (1 or 2 layers) + max over k ----------------
// block = 256 threads = 4 points x 64 output channels
template<int CIN, bool TWO>
__global__ __launch_bounds__(256) void edgeconv_kernel(
    const float* __restrict__ x, const int* __restrict__ knn,
    const float* __restrict__ wa, const float* __restrict__ wb,
    const float* __restrict__ pa, int ia, float* __restrict__ out)
{
    __shared__ float swa[2*CIN*64];
    __shared__ float sxi[4][CIN];
    __shared__ float sxj[4][CIN];
    __shared__ float sh1[4][64];

    const int tid = threadIdx.x;
    const int c = tid & 63;
    const int p = tid >> 6;

    for (int i = tid; i < 2*CIN*64; i += 256) swa[i] = wa[i];

    float wbcol[(TWO ? 64 : 1)];
    if (TWO){
#pragma unroll
        for (int d = 0; d < 64; d++) wbcol[d] = wb[d*64 + c];
    }
    const float aa = pa[ia];
    const float ab = TWO ? pa[ia+1] : 0.f;

    const int gp = blockIdx.x*4 + p;          // [0, MTOT)
    const int b  = gp >> 13;                  // N = 8192
    const int n  = gp & (NN-1);
    const float* xb = x + (size_t)b*NN*CIN;

    for (int i = c; i < CIN; i += 64) sxi[p][i] = xb[(size_t)n*CIN + i];

    float maxv = -FLT_MAX;
    const int* krow = knn + (size_t)gp*KNN;

    for (int kk = 0; kk < KNN; kk++){
        int j = krow[kk];
        __syncthreads();   // previous iteration finished reading sxj / sh1
        for (int i = c; i < CIN; i += 64) sxj[p][i] = xb[(size_t)j*CIN + i];
        __syncthreads();

        float acc = 0.f;
#pragma unroll
        for (int d = 0; d < CIN; d++){
            float xi = sxi[p][d], xj = sxj[p][d];
            acc = fmaf(xj - xi, swa[d*64 + c], acc);
            acc = fmaf(xi, swa[(CIN + d)*64 + c], acc);
        }
        float h = prelu_f(acc, aa);

        if (TWO){
            sh1[p][c] = h;
            __syncthreads();
            float a2 = 0.f;
#pragma unroll
            for (int d = 0; d < 64; d++) a2 = fmaf(sh1[p][d], wbcol[d], a2);
            h = prelu_f(a2, ab);
        }
        maxv = fmaxf(maxv, h);
    }
    out[(size_t)gp*64 + c] = maxv;
}

// ---------------- init x5max to encoded -inf (0) ----------------
__global__ void init_x5max_kernel(){
    int i = blockIdx.x*256 + threadIdx.x;
    if (i < BB*1024) g_x5max[i] = 0u;
}

// ---------------- GEMM over K=192 with A gathered from x1|x2|x3 ----------------
// BM=64, BN=64, BK=16, 256 threads, 4x4 microtile.
// COLMAX: prelu then per-batch column max -> atomicMax (w6 path, no store)
// else:   acc + bias[b][col], prelu, store (w7 path)
template<bool COLMAX>
__global__ __launch_bounds__(256) void gemm192_kernel(
    const float* __restrict__ A1, const float* __restrict__ A2, const float* __restrict__ A3,
    const float* __restrict__ W, int Nc,
    const float* __restrict__ bias,
    float* __restrict__ Cout, int ldc,
    const float* __restrict__ pa, int ia)
{
    __shared__ __align__(16) float As[16][64];
    __shared__ __align__(16) float Ws[16][64];
    __shared__ float smax[16][64];

    const int tid = threadIdx.x;
    const int tx = tid & 15, ty = tid >> 4;
    const int col0 = blockIdx.x*64, row0 = blockIdx.y*64;
    const int b = row0 >> 13;
    const float slope = pa[ia];

    float acc[4][4];
#pragma unroll
    for (int i = 0; i < 4; i++)
#pragma unroll
        for (int j = 0; j < 4; j++) acc[i][j] = 0.f;

    const int lr  = tid >> 2;        // 0..63 tile row
    const int lk4 = (tid & 3)*4;     // k offset within BK

    for (int k0 = 0; k0 < 192; k0 += 16){
        const float* src; int koff;
        if (k0 < 64)      { src = A1; koff = k0;       }
        else if (k0 < 128){ src = A2; koff = k0 - 64;  }
        else              { src = A3; koff = k0 - 128; }
        float4 av = *(const float4*)&src[(size_t)(row0 + lr)*64 + koff + lk4];
        float4 wv = *(const float4*)&W[(size_t)(k0 + (tid >> 4))*Nc + col0 + (tid & 15)*4];
        __syncthreads();
        As[lk4+0][lr] = av.x; As[lk4+1][lr] = av.y; As[lk4+2][lr] = av.z; As[lk4+3][lr] = av.w;
        *(float4*)&Ws[tid >> 4][(tid & 15)*4] = wv;
        __syncthreads();
#pragma unroll
        for (int kk = 0; kk < 16; kk++){
            float a[4], w[4];
            *(float4*)a = *(const float4*)&As[kk][ty*4];
            *(float4*)w = *(const float4*)&Ws[kk][tx*4];
#pragma unroll
            for (int i = 0; i < 4; i++)
#pragma unroll
                for (int j = 0; j < 4; j++) acc[i][j] = fmaf(a[i], w[j], acc[i][j]);
        }
    }

    if (!COLMAX){
        float bj[4];
#pragma unroll
        for (int j = 0; j < 4; j++) bj[j] = bias ? bias[b*Nc + col0 + tx*4 + j] : 0.f;
#pragma unroll
        for (int i = 0; i < 4; i++){
#pragma unroll
            for (int j = 0; j < 4; j++){
                float v = acc[i][j] + bj[j];
                v = prelu_f(v, slope);
                Cout[(size_t)(row0 + ty*4 + i)*ldc + col0 + tx*4 + j] = v;
            }
        }
    } else {
#pragma unroll
        for (int j = 0; j < 4; j++){
            float m = -FLT_MAX;
#pragma unroll
            for (int i = 0; i < 4; i++) m = fmaxf(m, prelu_f(acc[i][j], slope));
            smax[ty][tx*4 + j] = m;
        }
        __syncthreads();
        if (ty == 0){
#pragma unroll
            for (int j = 0; j < 4; j++){
                float mm = smax[0][tx*4 + j];
#pragma unroll
                for (int t = 1; t < 16; t++) mm = fmaxf(mm, smax[t][tx*4 + j]);
                atomicMax(&g_x5max[b*1024 + col0 + tx*4 + j], enc_f(mm));
            }
        }
    }
}

// ---------------- bias7[b][c] = sum_d x5max[b][d] * w7[192+d][c] ----------------
__global__ __launch_bounds__(256) void bias7_kernel(const float* __restrict__ w7){
    int b = blockIdx.x, c = threadIdx.x;
    float acc = 0.f;
    for (int d = 0; d < 1024; d++){
        float v = dec_f(g_x5max[b*1024 + d]);
        acc = fmaf(v, w7[(size_t)(192 + d)*256 + c], acc);
    }
    g_bias7[b*256 + c] = acc;
}

// ---------------- generic fp32 GEMM + prelu (w8, w9) ----------------
__global__ __launch_bounds__(256) void gemm_kernel(
    const float* __restrict__ A, int lda,
    const float* __restrict__ W, int Nc, int Kd,
    float* __restrict__ Cout, int ldc,
    const float* __restrict__ pa, int ia)
{
    __shared__ __align__(16) float As[16][64];
    __shared__ __align__(16) float Ws[16][64];

    const int tid = threadIdx.x;
    const int tx = tid & 15, ty = tid >> 4;
    const int col0 = blockIdx.x*64, row0 = blockIdx.y*64;
    const float slope = pa[ia];

    float acc[4][4];
#pragma unroll
    for (int i = 0; i < 4; i++)
#pragma unroll
        for (int j = 0; j < 4; j++) acc[i][j] = 0.f;

    const int lr  = tid >> 2;
    const int lk4 = (tid & 3)*4;

    for (int k0 = 0; k0 < Kd; k0 += 16){
        float4 av = *(const float4*)&A[(size_t)(row0 + lr)*lda + k0 + lk4];
        float4 wv = *(const float4*)&W[(size_t)(k0 + (tid >> 4))*Nc + col0 + (tid & 15)*4];
        __syncthreads();
        As[lk4+0][lr] = av.x; As[lk4+1][lr] = av.y; As[lk4+2][lr] = av.z; As[lk4+3][lr] = av.w;
        *(float4*)&Ws[tid >> 4][(tid & 15)*4] = wv;
        __syncthreads();
#pragma unroll
        for (int kk = 0; kk < 16; kk++){
            float a[4], w[4];
            *(float4*)a = *(const float4*)&As[kk][ty*4];
            *(float4*)w = *(const float4*)&Ws[kk][tx*4];
#pragma unroll
            for (int i = 0; i < 4; i++)
#pragma unroll
                for (int j = 0; j < 4; j++) acc[i][j] = fmaf(a[i], w[j], acc[i][j]);
        }
    }
#pragma unroll
    for (int i = 0; i < 4; i++)
#pragma unroll
        for (int j = 0; j < 4; j++){
            float v = prelu_f(acc[i][j], slope);
            Cout[(size_t)(row0 + ty*4 + i)*ldc + col0 + tx*4 + j] = v;
        }
}

// ---------------- final layer: [M,128] @ w10[128,2] + prelu -> d_out ----------------
__global__ __launch_bounds__(256) void head_out_kernel(
    const float* __restrict__ yc, const float* __restrict__ w10,
    const float* __restrict__ pa, float* __restrict__ out)
{
    __shared__ float sw[256];
    if (threadIdx.x < 256) sw[threadIdx.x] = w10[threadIdx.x];
    __syncthreads();
    const float slope = pa[9];
    const int row = blockIdx.x*256 + threadIdx.x;   // M = 32768, 128 blocks
    const float* yr = yc + (size_t)row*128;
    float a0 = 0.f, a1 = 0.f;
#pragma unroll
    for (int d = 0; d < 128; d++){
        float v = yr[d];
        a0 = fmaf(v, sw[2*d + 0], a0);
        a1 = fmaf(v, sw[2*d + 1], a1);
    }
    out[row*2 + 0] = prelu_f(a0, slope);
    out[row*2 + 1] = prelu_f(a1, slope);
}

// ---------------- host orchestration ----------------
extern "C" void kernel_launch(void* const* d_in, const int* in_sizes, int n_in,
                              void* d_out, int out_size)
{
    (void)in_sizes; (void)n_in; (void)out_size;
    const float* targets = (const float*)d_in[0];
    const float* w[10];
    for (int i = 0; i < 10; i++) w[i] = (const float*)d_in[1 + i];
    const float* pa = (const float*)d_in[11];
    float* out = (float*)d_out;

    void *px0, *px1, *px2, *px3, *pknn, *pya, *pyb, *pb7;
    cudaGetSymbolAddress(&px0, g_x0);
    cudaGetSymbolAddress(&px1, g_x1);
    cudaGetSymbolAddress(&px2, g_x2);
    cudaGetSymbolAddress(&px3, g_x3);
    cudaGetSymbolAddress(&pknn, g_knn);
    cudaGetSymbolAddress(&pya, g_ya);
    cudaGetSymbolAddress(&pyb, g_yb);
    cudaGetSymbolAddress(&pb7, g_bias7);

    float* x0 = (float*)px0; float* x1 = (float*)px1;
    float* x2 = (float*)px2; float* x3 = (float*)px3;
    int*   kn = (int*)pknn;
    float* ya = (float*)pya; float* yb = (float*)pyb;
    float* b7 = (float*)pb7;

    // 1. x0 = [targets, targets]
    build_x0_kernel<<<MTOT/256, 256>>>(targets);

    // 2. EdgeConv stage 1 (C=6, two layers w1,w2)
    knn_kernel<6><<<dim3(NN/256, BB), 256>>>(x0, kn);
    edgeconv_kernel<6, true><<<MTOT/4, 256>>>(x0, kn, w[0], w[1], pa, 0, x1);

    // 3. EdgeConv stage 2 (C=64, two layers w3,w4)
    knn_kernel<64><<<dim3(NN/256, BB), 256>>>(x1, kn);
    edgeconv_kernel<64, true><<<MTOT/4, 256>>>(x1, kn, w[2], w[3], pa, 2, x2);

    // 4. EdgeConv stage 3 (C=64, one layer w5)
    knn_kernel<64><<<dim3(NN/256, BB), 256>>>(x2, kn);
    edgeconv_kernel<64, false><<<MTOT/4, 256>>>(x2, kn, w[4], nullptr, pa, 4, x3);

    // 5. x5max[b][:] = max_n prelu([x1,x2,x3] @ w6)   (fused colmax, no x5 materialization)
    init_x5max_kernel<<<(BB*1024 + 255)/256, 256>>>();
    gemm192_kernel<true><<<dim3(1024/64, MTOT/64), 256>>>(
        x1, x2, x3, w[5], 1024, nullptr, nullptr, 0, pa, 5);

    // 6. bias7[b] = x5max[b] @ w7[192:1216]
    bias7_kernel<<<BB, 256>>>(w[6]);

    // 7. ya = prelu([x1,x2,x3] @ w7[:192] + bias7)
    gemm192_kernel<false><<<dim3(256/64, MTOT/64), 256>>>(
        x1, x2, x3, w[6], 256, b7, ya, 256, pa, 6);

    // 8. yb = prelu(ya @ w8)
    gemm_kernel<<<dim3(256/64, MTOT/64), 256>>>(ya, 256, w[7], 256, 256, yb, 256, pa, 7);

    // 9. ya[:, :128] = prelu(yb @ w9)
    gemm_kernel<<<dim3(128/64, MTOT/64), 256>>>(yb, 256, w[8], 128, 256, ya, 128, pa, 8);

    // 10. out = prelu(ya128 @ w10)
    head_out_kernel<<<MTOT/256, 256>>>(ya, w[9], pa, out);
}

// round 3
// speedup vs baseline: 1.1308x; 1.1308x over previous
#include <cuda_runtime.h>
#include <cfloat>
#include <cstdint>
#include <math.h>

#define BB 4
#define NN 8192
#define KNN 10
#define MTOT (BB*NN)
#define LDD 129   // padded row stride of distance staging tile

// ---------------- scratch (device globals; no allocation allowed) ----------------
__device__ float    g_x0p[MTOT*8];      // [t,t,0,0] padded to 8 channels
__device__ float    g_x1[MTOT*64];
__device__ float    g_x2[MTOT*64];
__device__ float    g_x3[MTOT*64];
__device__ float    g_u[MTOT*64];
__device__ float    g_v[MTOT*64];
__device__ float    g_nrm[MTOT];
__device__ int      g_knn[MTOT*KNN];
__device__ unsigned g_x5max[BB*1024];   // ordered-uint encoded float max
__device__ float    g_bias7[BB*256];
__device__ float    g_ya[MTOT*256];
__device__ float    g_yb[MTOT*256];

// ---------------- helpers ----------------
__device__ __forceinline__ float prelu_f(float v, float a){ return v >= 0.f ? v : a*v; }

__device__ __forceinline__ unsigned enc_f(float f){
    unsigned u = __float_as_uint(f);
    return (u & 0x80000000u) ? ~u : (u | 0x80000000u);
}
__device__ __forceinline__ float dec_f(unsigned u){
    return (u & 0x80000000u) ? __uint_as_float(u & 0x7fffffffu) : __uint_as_float(~u);
}

// register top-10 insertion (ascending; ties keep earlier/lower index)
__device__ __forceinline__ void topk_insert(float (&dist)[KNN], int (&idx)[KNN], float d, int j){
    if (d < dist[KNN-1]){
        float cd = d; int cj = j;
#pragma unroll
        for (int p = 0; p < KNN; p++){
            if (cd < dist[p]){
                float td = dist[p]; int tj = idx[p];
                dist[p] = cd; idx[p] = cj;
                cd = td; cj = tj;
            }
        }
    }
}

// ---------------- build x0p = [t,t,0,0] padded to 8 ----------------
__global__ __launch_bounds__(256) void build_x0p_kernel(const float* __restrict__ t){
    int i = blockIdx.x*256 + threadIdx.x;
    float t0 = t[i*3+0], t1 = t[i*3+1], t2 = t[i*3+2];
    float4* o = (float4*)(g_x0p + (size_t)i*8);
    o[0] = make_float4(t0, t1, t2, t0);
    o[1] = make_float4(t1, t2, 0.f, 0.f);
}

// ---------------- row squared norms ----------------
template<int KCH>
__global__ __launch_bounds__(256) void norms_kernel(const float* __restrict__ x, float* __restrict__ nrm){
    int r = blockIdx.x*256 + threadIdx.x;
    const float* xr = x + (size_t)r*KCH;
    float s = 0.f;
#pragma unroll
    for (int k = 0; k < KCH; k++) s = fmaf(xr[k], xr[k], s);
    nrm[r] = s;
}

// ---------------- kNN: GEMM-tiled distances + in-register top-10 ----------------
// Block: 256 threads, 128 queries, full candidate sweep in 128-tiles.
// GEMM phase: 8x8 microtile ({ty*4, 64+ty*4} x {tx*4, 64+tx*4}) from k-major smem tiles.
// Topk phase: thread t owns query (t&127), half (t>>7); scans staged distances.
template<int KCH>
__global__ __launch_bounds__(256, 1) void knn_tile_kernel(
    const float* __restrict__ x, const float* __restrict__ nrm, int* __restrict__ knnout)
{
    extern __shared__ float sm[];
    float* Qs = sm;                    // KCH*128  (k-major)
    float* Cs = Qs + KCH*128;          // KCH*128
    float* qn = Cs + KCH*128;          // 128
    float* cn = qn + 128;              // 128
    float* D  = cn + 128;              // 128*LDD

    const int tid = threadIdx.x;
    const int b   = blockIdx.y;
    const int q0  = blockIdx.x*128;
    const float* xb = x + (size_t)b*NN*KCH;
    const float* nb = nrm + (size_t)b*NN;

    // load Q tile (transposed to k-major)
    constexpr int NV = 128*(KCH/4);
    for (int f = tid; f < NV; f += 256){
        int row = f & 127;
        int kq  = (f >> 7) * 4;
        float4 v = *(const float4*)&xb[(size_t)(q0+row)*KCH + kq];
        Qs[(kq+0)*128+row]=v.x; Qs[(kq+1)*128+row]=v.y;
        Qs[(kq+2)*128+row]=v.z; Qs[(kq+3)*128+row]=v.w;
    }
    if (tid < 128) qn[tid] = nb[q0 + tid];

    float dist[KNN]; int idx[KNN];
#pragma unroll
    for (int i = 0; i < KNN; i++){ dist[i] = FLT_MAX; idx[i] = 0x7fffffff; }

    const int ty = tid >> 4;      // 0..15
    const int tx = tid & 15;
    int rr[8], cc[8];
#pragma unroll
    for (int i = 0; i < 4; i++){ rr[i] = ty*4 + i; rr[i+4] = 64 + ty*4 + i; }
#pragma unroll
    for (int j = 0; j < 4; j++){ cc[j] = tx*4 + j; cc[j+4] = 64 + tx*4 + j; }
    const int qh = tid & 127;     // topk: owned query (local)
    const int hh = tid >> 7;      // topk: half

    for (int ct = 0; ct < NN; ct += 128){
        __syncthreads();   // prior-iter D/Cs consumers done
        for (int f = tid; f < NV; f += 256){
            int row = f & 127;
            int kq  = (f >> 7) * 4;
            float4 v = *(const float4*)&xb[(size_t)(ct+row)*KCH + kq];
            Cs[(kq+0)*128+row]=v.x; Cs[(kq+1)*128+row]=v.y;
            Cs[(kq+2)*128+row]=v.z; Cs[(kq+3)*128+row]=v.w;
        }
        if (tid < 128) cn[tid] = nb[ct + tid];
        __syncthreads();

        float acc[8][8];
#pragma unroll
        for (int i = 0; i < 8; i++)
#pragma unroll
            for (int j = 0; j < 8; j++) acc[i][j] = 0.f;

#pragma unroll 8
        for (int k = 0; k < KCH; k++){
            float a[8], bb[8];
            *(float4*)&a[0]  = *(const float4*)&Qs[k*128 + ty*4];
            *(float4*)&a[4]  = *(const float4*)&Qs[k*128 + 64 + ty*4];
            *(float4*)&bb[0] = *(const float4*)&Cs[k*128 + tx*4];
            *(float4*)&bb[4] = *(const float4*)&Cs[k*128 + 64 + tx*4];
#pragma unroll
            for (int i = 0; i < 8; i++)
#pragma unroll
                for (int j = 0; j < 8; j++) acc[i][j] = fmaf(a[i], bb[j], acc[i][j]);
        }

        // epilogue: stage distances
        float qv[8], cv[8];
#pragma unroll
        for (int i = 0; i < 8; i++) qv[i] = qn[rr[i]];
#pragma unroll
        for (int j = 0; j < 8; j++) cv[j] = cn[cc[j]];
#pragma unroll
        for (int i = 0; i < 8; i++)
#pragma unroll
            for (int j = 0; j < 8; j++)
                D[rr[i]*LDD + cc[j]] = (qv[i] + cv[j]) - 2.f*acc[i][j];
        __syncthreads();

        // topk scan: 2 threads per query, 64 candidates each
        const float* drow = &D[qh*LDD + hh*64];
        const int cbase = ct + hh*64;
#pragma unroll 4
        for (int i = 0; i < 64; i++)
            topk_insert(dist, idx, drow[i], cbase + i);
    }

    // merge the two half-lists per query (stable, exact)
    __syncthreads();
    float* Ld = D;                 // 2560 floats
    int*   Li = (int*)(D + 4096);  // 2560 ints
#pragma unroll
    for (int i = 0; i < KNN; i++){ Ld[tid*KNN + i] = dist[i]; Li[tid*KNN + i] = idx[i]; }
    __syncthreads();
    if (tid < 128){
        const float* da = &Ld[tid*KNN];        const int* ja = &Li[tid*KNN];
        const float* db = &Ld[(tid+128)*KNN];  const int* jb = &Li[(tid+128)*KNN];
        int* ko = knnout + ((size_t)b*NN + q0 + tid)*KNN;
        int ia = 0, ib = 0;
#pragma unroll
        for (int i = 0; i < KNN; i++){
            float d0 = da[ia], d1 = db[ib];
            int   j0 = ja[ia], j1 = jb[ib];
            bool A = (d0 < d1) || (d0 == d1 && j0 < j1);
            ko[i] = A ? j0 : j1;
            if (A) ia++; else ib++;
        }
    }
}

// ---------------- uv precompute: v = x@Wa, u = x@(Wb - Wa) ----------------
// w layout [2*CIN][64]; block = 4 points x 64 channels
template<int CIN>
__global__ __launch_bounds__(256) void uv_kernel(
    const float* __restrict__ x, int xs, const float* __restrict__ w,
    float* __restrict__ u, float* __restrict__ v)
{
    __shared__ float sW1[CIN*64];
    __shared__ float sW2[CIN*64];
    __shared__ float sx[4][CIN];
    const int tid = threadIdx.x;
    const int p = tid >> 6, c = tid & 63;
    for (int i = tid; i < CIN*64; i += 256){
        float a = w[i];
        sW1[i] = a;
        sW2[i] = w[CIN*64 + i] - a;
    }
    const int gp = blockIdx.x*4 + p;
    for (int i = c; i < CIN; i += 64) sx[p][i] = x[(size_t)gp*xs + i];
    __syncthreads();
    float uu = 0.f, vv = 0.f;
#pragma unroll
    for (int d = 0; d < CIN; d++){
        float xv = sx[p][d];
        vv = fmaf(xv, sW1[d*64 + c], vv);
        uu = fmaf(xv, sW2[d*64 + c], uu);
    }
    u[(size_t)gp*64 + c] = uu;
    v[(size_t)gp*64 + c] = vv;
}

// ---------------- 2-layer edgeconv tail: h1 = prelu(u_i+v_j), h2 = prelu(h1@W2), max_k ----------------
__global__ __launch_bounds__(256) void edge2_kernel(
    const float* __restrict__ u, const float* __restrict__ v,
    const int* __restrict__ knn, const float* __restrict__ w2,
    const float* __restrict__ pa, int ia, float* __restrict__ out)
{
    __shared__ float sh1[4][64];
    const int tid = threadIdx.x;
    const int p = tid >> 6, c = tid & 63;
    float wcol[64];
#pragma unroll
    for (int d = 0; d < 64; d++) wcol[d] = __ldg(&w2[d*64 + c]);
    const float a1 = pa[ia], a2 = pa[ia+1];
    const int gp = blockIdx.x*4 + p;
    const int b  = gp >> 13;
    const float* vb = v + (size_t)b*NN*64;
    const float ur = u[(size_t)gp*64 + c];
    const int* krow = knn + (size_t)gp*KNN;
    float maxv = -FLT_MAX;
#pragma unroll
    for (int kk = 0; kk < KNN; kk++){
        int j = krow[kk];
        float h = prelu_f(ur + vb[(size_t)j*64 + c], a1);
        __syncthreads();
        sh1[p][c] = h;
        __syncthreads();
        float acc = 0.f;
#pragma unroll
        for (int d = 0; d < 64; d += 4){
            float4 hv = *(const float4*)&sh1[p][d];
            acc = fmaf(hv.x, wcol[d+0], acc);
            acc = fmaf(hv.y, wcol[d+1], acc);
            acc = fmaf(hv.z, wcol[d+2], acc);
            acc = fmaf(hv.w, wcol[d+3], acc);
        }
        maxv = fmaxf(maxv, prelu_f(acc, a2));
    }
    out[(size_t)gp*64 + c] = maxv;
}

// ---------------- 1-layer edgeconv tail: max_k prelu(u_i + v_j) ----------------
__global__ __launch_bounds__(256) void edge1_kernel(
    const float* __restrict__ u, const float* __restrict__ v,
    const int* __restrict__ knn, const float* __restrict__ pa, int ia,
    float* __restrict__ out)
{
    const int tid = threadIdx.x;
    const int p = tid >> 6, c = tid & 63;
    const float a1 = pa[ia];
    const int gp = blockIdx.x*4 + p;
    const int b  = gp >> 13;
    const float* vb = v + (size_t)b*NN*64;
    const float ur = u[(size_t)gp*64 + c];
    const int* krow = knn + (size_t)gp*KNN;
    float maxv = -FLT_MAX;
#pragma unroll
    for (int kk = 0; kk < KNN; kk++){
        int j = krow[kk];
        maxv = fmaxf(maxv, prelu_f(ur + vb[(size_t)j*64 + c], a1));
    }
    out[(size_t)gp*64 + c] = maxv;
}

// ---------------- init x5max ----------------
__global__ void init_x5max_kernel(){
    int i = blockIdx.x*256 + threadIdx.x;
    if (i < BB*1024) g_x5max[i] = 0u;
}

// ---------------- GEMM over K=192 with A gathered from x1|x2|x3 ----------------
template<bool COLMAX>
__global__ __launch_bounds__(256) void gemm192_kernel(
    const float* __restrict__ A1, const float* __restrict__ A2, const float* __restrict__ A3,
    const float* __restrict__ W, int Nc,
    const float* __restrict__ bias,
    float* __restrict__ Cout, int ldc,
    const float* __restrict__ pa, int ia)
{
    __shared__ __align__(16) float As[16][64];
    __shared__ __align__(16) float Ws[16][64];
    __shared__ float smax[16][64];

    const int tid = threadIdx.x;
    const int tx = tid & 15, ty = tid >> 4;
    const int col0 = blockIdx.x*64, row0 = blockIdx.y*64;
    const int b = row0 >> 13;
    const float slope = pa[ia];

    float acc[4][4];
#pragma unroll
    for (int i = 0; i < 4; i++)
#pragma unroll
        for (int j = 0; j < 4; j++) acc[i][j] = 0.f;

    const int lr  = tid >> 2;
    const int lk4 = (tid & 3)*4;

    for (int k0 = 0; k0 < 192; k0 += 16){
        const float* src; int koff;
        if (k0 < 64)      { src = A1; koff = k0;       }
        else if (k0 < 128){ src = A2; koff = k0 - 64;  }
        else              { src = A3; koff = k0 - 128; }
        float4 av = *(const float4*)&src[(size_t)(row0 + lr)*64 + koff + lk4];
        float4 wv = *(const float4*)&W[(size_t)(k0 + (tid >> 4))*Nc + col0 + (tid & 15)*4];
        __syncthreads();
        As[lk4+0][lr] = av.x; As[lk4+1][lr] = av.y; As[lk4+2][lr] = av.z; As[lk4+3][lr] = av.w;
        *(float4*)&Ws[tid >> 4][(tid & 15)*4] = wv;
        __syncthreads();
#pragma unroll
        for (int kk = 0; kk < 16; kk++){
            float a[4], w[4];
            *(float4*)a = *(const float4*)&As[kk][ty*4];
            *(float4*)w = *(const float4*)&Ws[kk][tx*4];
#pragma unroll
            for (int i = 0; i < 4; i++)
#pragma unroll
                for (int j = 0; j < 4; j++) acc[i][j] = fmaf(a[i], w[j], acc[i][j]);
        }
    }

    if (!COLMAX){
        float bj[4];
#pragma unroll
        for (int j = 0; j < 4; j++) bj[j] = bias ? bias[b*Nc + col0 + tx*4 + j] : 0.f;
#pragma unroll
        for (int i = 0; i < 4; i++){
#pragma unroll
            for (int j = 0; j < 4; j++){
                float v = acc[i][j] + bj[j];
                v = prelu_f(v, slope);
                Cout[(size_t)(row0 + ty*4 + i)*ldc + col0 + tx*4 + j] = v;
            }
        }
    } else {
#pragma unroll
        for (int j = 0; j < 4; j++){
            float m = -FLT_MAX;
#pragma unroll
            for (int i = 0; i < 4; i++) m = fmaxf(m, prelu_f(acc[i][j], slope));
            smax[ty][tx*4 + j] = m;
        }
        __syncthreads();
        if (ty == 0){
#pragma unroll
            for (int j = 0; j < 4; j++){
                float mm = smax[0][tx*4 + j];
#pragma unroll
                for (int t = 1; t < 16; t++) mm = fmaxf(mm, smax[t][tx*4 + j]);
                atomicMax(&g_x5max[b*1024 + col0 + tx*4 + j], enc_f(mm));
            }
        }
    }
}

// ---------------- bias7 ----------------
__global__ __launch_bounds__(256) void bias7_kernel(const float* __restrict__ w7){
    int b = blockIdx.x, c = threadIdx.x;
    float acc = 0.f;
    for (int d = 0; d < 1024; d++){
        float v = dec_f(g_x5max[b*1024 + d]);
        acc = fmaf(v, w7[(size_t)(192 + d)*256 + c], acc);
    }
    g_bias7[b*256 + c] = acc;
}

// ---------------- generic fp32 GEMM + prelu ----------------
__global__ __launch_bounds__(256) void gemm_kernel(
    const float* __restrict__ A, int lda,
    const float* __restrict__ W, int Nc, int Kd,
    float* __restrict__ Cout, int ldc,
    const float* __restrict__ pa, int ia)
{
    __shared__ __align__(16) float As[16][64];
    __shared__ __align__(16) float Ws[16][64];

    const int tid = threadIdx.x;
    const int tx = tid & 15, ty = tid >> 4;
    const int col0 = blockIdx.x*64, row0 = blockIdx.y*64;
    const float slope = pa[ia];

    float acc[4][4];
#pragma unroll
    for (int i = 0; i < 4; i++)
#pragma unroll
        for (int j = 0; j < 4; j++) acc[i][j] = 0.f;

    const int lr  = tid >> 2;
    const int lk4 = (tid & 3)*4;

    for (int k0 = 0; k0 < Kd; k0 += 16){
        float4 av = *(const float4*)&A[(size_t)(row0 + lr)*lda + k0 + lk4];
        float4 wv = *(const float4*)&W[(size_t)(k0 + (tid >> 4))*Nc + col0 + (tid & 15)*4];
        __syncthreads();
        As[lk4+0][lr] = av.x; As[lk4+1][lr] = av.y; As[lk4+2][lr] = av.z; As[lk4+3][lr] = av.w;
        *(float4*)&Ws[tid >> 4][(tid & 15)*4] = wv;
        __syncthreads();
#pragma unroll
        for (int kk = 0; kk < 16; kk++){
            float a[4], w[4];
            *(float4*)a = *(const float4*)&As[kk][ty*4];
            *(float4*)w = *(const float4*)&Ws[kk][tx*4];
#pragma unroll
            for (int i = 0; i < 4; i++)
#pragma unroll
                for (int j = 0; j < 4; j++) acc[i][j] = fmaf(a[i], w[j], acc[i][j]);
        }
    }
#pragma unroll
    for (int i = 0; i < 4; i++)
#pragma unroll
        for (int j = 0; j < 4; j++){
            float v = prelu_f(acc[i][j], slope);
            Cout[(size_t)(row0 + ty*4 + i)*ldc + col0 + tx*4 + j] = v;
        }
}

// ---------------- final layer ----------------
__global__ __launch_bounds__(256) void head_out_kernel(
    const float* __restrict__ yc, const float* __restrict__ w10,
    const float* __restrict__ pa, float* __restrict__ out)
{
    __shared__ float sw[256];
    if (threadIdx.x < 256) sw[threadIdx.x] = w10[threadIdx.x];
    __syncthreads();
    const float slope = pa[9];
    const int row = blockIdx.x*256 + threadIdx.x;
    const float* yr = yc + (size_t)row*128;
    float a0 = 0.f, a1 = 0.f;
#pragma unroll
    for (int d = 0; d < 128; d++){
        float v = yr[d];
        a0 = fmaf(v, sw[2*d + 0], a0);
        a1 = fmaf(v, sw[2*d + 1], a1);
    }
    out[row*2 + 0] = prelu_f(a0, slope);
    out[row*2 + 1] = prelu_f(a1, slope);
}

// ---------------- host orchestration ----------------
extern "C" void kernel_launch(void* const* d_in, const int* in_sizes, int n_in,
                              void* d_out, int out_size)
{
    (void)in_sizes; (void)n_in; (void)out_size;
    const float* targets = (const float*)d_in[0];
    const float* w[10];
    for (int i = 0; i < 10; i++) w[i] = (const float*)d_in[1 + i];
    const float* pa = (const float*)d_in[11];
    float* out = (float*)d_out;

    void *px0, *px1, *px2, *px3, *pu, *pv, *pn, *pknn, *pya, *pyb, *pb7;
    cudaGetSymbolAddress(&px0, g_x0p);
    cudaGetSymbolAddress(&px1, g_x1);
    cudaGetSymbolAddress(&px2, g_x2);
    cudaGetSymbolAddress(&px3, g_x3);
    cudaGetSymbolAddress(&pu,  g_u);
    cudaGetSymbolAddress(&pv,  g_v);
    cudaGetSymbolAddress(&pn,  g_nrm);
    cudaGetSymbolAddress(&pknn, g_knn);
    cudaGetSymbolAddress(&pya, g_ya);
    cudaGetSymbolAddress(&pyb, g_yb);
    cudaGetSymbolAddress(&pb7, g_bias7);

    float* x0 = (float*)px0; float* x1 = (float*)px1;
    float* x2 = (float*)px2; float* x3 = (float*)px3;
    float* uu = (float*)pu;  float* vv = (float*)pv;
    float* nr = (float*)pn;
    int*   kn = (int*)pknn;
    float* ya = (float*)pya; float* yb = (float*)pyb;
    float* b7 = (float*)pb7;

    // opt-in to large dynamic smem for kNN kernels (idempotent)
    const int SM8  = (8*128*2 + 256)*4 + 128*LDD*4;
    const int SM64 = (64*128*2 + 256)*4 + 128*LDD*4;
    cudaFuncSetAttribute(knn_tile_kernel<8>,  cudaFuncAttributeMaxDynamicSharedMemorySize, SM8);
    cudaFuncSetAttribute(knn_tile_kernel<64>, cudaFuncAttributeMaxDynamicSharedMemorySize, SM64);

    dim3 kgrid(NN/128, BB);

    // stage 0: x0p = [t,t,0,0]
    build_x0p_kernel<<<MTOT/256, 256>>>(targets);

    // stage 1 (CIN=6 via padded 8)
    norms_kernel<8><<<MTOT/256, 256>>>(x0, nr);
    knn_tile_kernel<8><<<kgrid, 256, SM8>>>(x0, nr, kn);
    uv_kernel<6><<<MTOT/4, 256>>>(x0, 8, w[0], uu, vv);
    edge2_kernel<<<MTOT/4, 256>>>(uu, vv, kn, w[1], pa, 0, x1);

    // stage 2
    norms_kernel<64><<<MTOT/256, 256>>>(x1, nr);
    knn_tile_kernel<64><<<kgrid, 256, SM64>>>(x1, nr, kn);
    uv_kernel<64><<<MTOT/4, 256>>>(x1, 64, w[2], uu, vv);
    edge2_kernel<<<MTOT/4, 256>>>(uu, vv, kn, w[3], pa, 2, x2);

    // stage 3 (single layer)
    norms_kernel<64><<<MTOT/256, 256>>>(x2, nr);
    knn_tile_kernel<64><<<kgrid, 256, SM64>>>(x2, nr, kn);
    uv_kernel<64><<<MTOT/4, 256>>>(x2, 64, w[4], uu, vv);
    edge1_kernel<<<MTOT/4, 256>>>(uu, vv, kn, pa, 4, x3);

    // head
    init_x5max_kernel<<<(BB*1024 + 255)/256, 256>>>();
    gemm192_kernel<true><<<dim3(1024/64, MTOT/64), 256>>>(
        x1, x2, x3, w[5], 1024, nullptr, nullptr, 0, pa, 5);
    bias7_kernel<<<BB, 256>>>(w[6]);
    gemm192_kernel<false><<<dim3(256/64, MTOT/64), 256>>>(
        x1, x2, x3, w[6], 256, b7, ya, 256, pa, 6);
    gemm_kernel<<<dim3(256/64, MTOT/64), 256>>>(ya, 256, w[7], 256, 256, yb, 256, pa, 7);
    gemm_kernel<<<dim3(128/64, MTOT/64), 256>>>(yb, 256, w[8], 128, 256, ya, 128, pa, 8);
    head_out_kernel<<<MTOT/256, 256>>>(ya, w[9], pa, out);
}